// round 4
// baseline (speedup 1.0000x reference)
#include <cuda_runtime.h>

// PixCorr: per-row Pearson correlation over [256, 196608] fp32 rows,
// then mean of the 256 correlations. Single fused kernel:
//  - one CTA per row streams its 1.57 MB (x2 tensors) with float4 __ldcs
//    loads, accumulating 5 running sums (sz, sb, szz, sbb, szb).
//  - block-reduce -> corr[row] into a __device__ global.
//  - last CTA to finish (atomic ticket) reduces the 256 corrs to the mean
//    and writes d_out[0]; resets the ticket for graph replay determinism.

#define NROWS   256
#define D_ELEMS 196608          // 3*256*256
#define NVEC    (D_ELEMS / 4)   // 49152 float4 per row
#define THREADS 1024
#define EPS     1e-6f

__device__ float        g_corr[NROWS];
__device__ unsigned int g_ticket;   // zero-initialized at module load

__device__ __forceinline__ float warp_sum(float v) {
    v += __shfl_xor_sync(0xFFFFFFFFu, v, 16);
    v += __shfl_xor_sync(0xFFFFFFFFu, v, 8);
    v += __shfl_xor_sync(0xFFFFFFFFu, v, 4);
    v += __shfl_xor_sync(0xFFFFFFFFu, v, 2);
    v += __shfl_xor_sync(0xFFFFFFFFu, v, 1);
    return v;
}

__device__ __forceinline__ float4 ldcs4(const float4* p) {
    float4 v;
    asm volatile("ld.global.cs.v4.f32 {%0,%1,%2,%3}, [%4];"
                 : "=f"(v.x), "=f"(v.y), "=f"(v.z), "=f"(v.w)
                 : "l"(p));
    return v;
}

__global__ __launch_bounds__(THREADS, 1)
void pixcorr_fused_kernel(const float* __restrict__ preds,
                          const float* __restrict__ targets,
                          float* __restrict__ out) {
    const int row = blockIdx.x;
    const float4* __restrict__ z4 =
        reinterpret_cast<const float4*>(targets + (size_t)row * D_ELEMS);
    const float4* __restrict__ b4 =
        reinterpret_cast<const float4*>(preds + (size_t)row * D_ELEMS);

    float sz = 0.f, sb = 0.f, szz = 0.f, sbb = 0.f, szb = 0.f;

    // 48 iterations per thread, coalesced 128-bit streaming loads.
    #pragma unroll 4
    for (int i = threadIdx.x; i < NVEC; i += THREADS) {
        float4 zv = ldcs4(z4 + i);
        float4 bv = ldcs4(b4 + i);
        sz  += (zv.x + zv.y) + (zv.z + zv.w);
        sb  += (bv.x + bv.y) + (bv.z + bv.w);
        szz  = fmaf(zv.x, zv.x, fmaf(zv.y, zv.y, fmaf(zv.z, zv.z, fmaf(zv.w, zv.w, szz))));
        sbb  = fmaf(bv.x, bv.x, fmaf(bv.y, bv.y, fmaf(bv.z, bv.z, fmaf(bv.w, bv.w, sbb))));
        szb  = fmaf(zv.x, bv.x, fmaf(zv.y, bv.y, fmaf(zv.z, bv.z, fmaf(zv.w, bv.w, szb))));
    }

    sz  = warp_sum(sz);
    sb  = warp_sum(sb);
    szz = warp_sum(szz);
    sbb = warp_sum(sbb);
    szb = warp_sum(szb);

    __shared__ float sh[5][THREADS / 32];
    __shared__ int   s_is_last;
    const int lane = threadIdx.x & 31;
    const int wid  = threadIdx.x >> 5;
    if (lane == 0) {
        sh[0][wid] = sz;  sh[1][wid] = sb;
        sh[2][wid] = szz; sh[3][wid] = sbb; sh[4][wid] = szb;
    }
    __syncthreads();

    if (threadIdx.x < 32) {
        float a0 = sh[0][lane];
        float a1 = sh[1][lane];
        float a2 = sh[2][lane];
        float a3 = sh[3][lane];
        float a4 = sh[4][lane];
        a0 = warp_sum(a0);
        a1 = warp_sum(a1);
        a2 = warp_sum(a2);
        a3 = warp_sum(a3);
        a4 = warp_sum(a4);
        if (lane == 0) {
            const float invD = 1.0f / (float)D_ELEMS;
            float cov = a4 - a0 * a1 * invD;
            float vz  = fmaxf(a2 - a0 * a0 * invD, 0.f);
            float vb  = fmaxf(a3 - a1 * a1 * invD, 0.f);
            g_corr[row] = cov / (sqrtf(vz) * sqrtf(vb) + EPS);

            // Make the corr visible, then take a ticket.
            __threadfence();
            unsigned int t = atomicAdd(&g_ticket, 1u);
            s_is_last = (t == NROWS - 1u) ? 1 : 0;
        }
    }
    __syncthreads();

    if (s_is_last) {
        // This CTA saw every other CTA's g_corr write (fence + atomic order).
        // Reduce 256 values using the first 256 threads.
        float v = 0.f;
        if (threadIdx.x < NROWS) v = g_corr[threadIdx.x];
        v = warp_sum(v);
        __shared__ float shm[THREADS / 32];
        if (lane == 0) shm[wid] = v;
        __syncthreads();
        if (threadIdx.x == 0) {
            float s = 0.f;
            #pragma unroll
            for (int i = 0; i < NROWS / 32; i++) s += shm[i];
            out[0] = s * (1.0f / (float)NROWS);
            g_ticket = 0;           // reset for next graph replay
            __threadfence();
        }
    }
}

extern "C" void kernel_launch(void* const* d_in, const int* in_sizes, int n_in,
                              void* d_out, int out_size) {
    const float* preds   = (const float*)d_in[0];
    const float* targets = (const float*)d_in[1];
    float* out = (float*)d_out;

    pixcorr_fused_kernel<<<NROWS, THREADS>>>(preds, targets, out);
}

// round 5
// speedup vs baseline: 1.0446x; 1.0446x over previous
#include <cuda_runtime.h>

// PixCorr: per-row Pearson correlation over [256, 196608] fp32 rows,
// then mean of the 256 correlations. Single fused kernel:
//  - one CTA per row streams its 2 x 768 KB with float4 __ldcs intrinsic
//    loads (schedulable by ptxas, unlike asm volatile), accumulating
//    5 running sums (sz, sb, szz, sbb, szb).
//  - block-reduce -> corr[row] into a __device__ global.
//  - last CTA to finish (atomic ticket) reduces the 256 corrs to the mean
//    and writes d_out[0]; resets the ticket for graph replay determinism.

#define NROWS   256
#define D_ELEMS 196608          // 3*256*256
#define NVEC    (D_ELEMS / 4)   // 49152 float4 per row
#define THREADS 1024
#define EPS     1e-6f

__device__ float        g_corr[NROWS];
__device__ unsigned int g_ticket;   // zero-initialized at module load

__device__ __forceinline__ float warp_sum(float v) {
    v += __shfl_xor_sync(0xFFFFFFFFu, v, 16);
    v += __shfl_xor_sync(0xFFFFFFFFu, v, 8);
    v += __shfl_xor_sync(0xFFFFFFFFu, v, 4);
    v += __shfl_xor_sync(0xFFFFFFFFu, v, 2);
    v += __shfl_xor_sync(0xFFFFFFFFu, v, 1);
    return v;
}

__global__ __launch_bounds__(THREADS, 1)
void pixcorr_fused_kernel(const float* __restrict__ preds,
                          const float* __restrict__ targets,
                          float* __restrict__ out) {
    const int row = blockIdx.x;
    const float4* __restrict__ z4 =
        reinterpret_cast<const float4*>(targets + (size_t)row * D_ELEMS);
    const float4* __restrict__ b4 =
        reinterpret_cast<const float4*>(preds + (size_t)row * D_ELEMS);

    float sz = 0.f, sb = 0.f, szz = 0.f, sbb = 0.f, szb = 0.f;

    // 48 iterations per thread, coalesced 128-bit streaming loads.
    // __ldcs intrinsic keeps the .cs evict-first hint while letting ptxas
    // batch the LDGs across unrolled iterations (high MLP).
    #pragma unroll 4
    for (int i = threadIdx.x; i < NVEC; i += THREADS) {
        float4 zv = __ldcs(z4 + i);
        float4 bv = __ldcs(b4 + i);
        sz  += (zv.x + zv.y) + (zv.z + zv.w);
        sb  += (bv.x + bv.y) + (bv.z + bv.w);
        szz  = fmaf(zv.x, zv.x, fmaf(zv.y, zv.y, fmaf(zv.z, zv.z, fmaf(zv.w, zv.w, szz))));
        sbb  = fmaf(bv.x, bv.x, fmaf(bv.y, bv.y, fmaf(bv.z, bv.z, fmaf(bv.w, bv.w, sbb))));
        szb  = fmaf(zv.x, bv.x, fmaf(zv.y, bv.y, fmaf(zv.z, bv.z, fmaf(zv.w, bv.w, szb))));
    }

    sz  = warp_sum(sz);
    sb  = warp_sum(sb);
    szz = warp_sum(szz);
    sbb = warp_sum(sbb);
    szb = warp_sum(szb);

    __shared__ float sh[5][THREADS / 32];
    __shared__ int   s_is_last;
    const int lane = threadIdx.x & 31;
    const int wid  = threadIdx.x >> 5;
    if (lane == 0) {
        sh[0][wid] = sz;  sh[1][wid] = sb;
        sh[2][wid] = szz; sh[3][wid] = sbb; sh[4][wid] = szb;
    }
    __syncthreads();

    if (threadIdx.x < 32) {
        float a0 = sh[0][lane];
        float a1 = sh[1][lane];
        float a2 = sh[2][lane];
        float a3 = sh[3][lane];
        float a4 = sh[4][lane];
        a0 = warp_sum(a0);
        a1 = warp_sum(a1);
        a2 = warp_sum(a2);
        a3 = warp_sum(a3);
        a4 = warp_sum(a4);
        if (lane == 0) {
            const float invD = 1.0f / (float)D_ELEMS;
            float cov = a4 - a0 * a1 * invD;
            float vz  = fmaxf(a2 - a0 * a0 * invD, 0.f);
            float vb  = fmaxf(a3 - a1 * a1 * invD, 0.f);
            g_corr[row] = cov / (sqrtf(vz) * sqrtf(vb) + EPS);

            // Make the corr visible, then take a ticket.
            __threadfence();
            unsigned int t = atomicAdd(&g_ticket, 1u);
            s_is_last = (t == NROWS - 1u) ? 1 : 0;
        }
    }
    __syncthreads();

    if (s_is_last) {
        // This CTA saw every other CTA's g_corr write (fence + atomic order).
        float v = 0.f;
        if (threadIdx.x < NROWS) v = g_corr[threadIdx.x];
        v = warp_sum(v);
        __shared__ float shm[THREADS / 32];
        if (lane == 0) shm[wid] = v;
        __syncthreads();
        if (threadIdx.x == 0) {
            float s = 0.f;
            #pragma unroll
            for (int i = 0; i < NROWS / 32; i++) s += shm[i];
            out[0] = s * (1.0f / (float)NROWS);
            g_ticket = 0;           // reset for next graph replay
            __threadfence();
        }
    }
}

extern "C" void kernel_launch(void* const* d_in, const int* in_sizes, int n_in,
                              void* d_out, int out_size) {
    const float* preds   = (const float*)d_in[0];
    const float* targets = (const float*)d_in[1];
    float* out = (float*)d_out;

    pixcorr_fused_kernel<<<NROWS, THREADS>>>(preds, targets, out);
}